// round 9
// baseline (speedup 1.0000x reference)
#include <cuda_runtime.h>
#include <math.h>

#define Bs   16
#define Cc   256
#define Hh   128
#define Ww   128
#define HW   16384
#define CHUNK 2          // batches per L2-blocked chunk (32MB scratch -> L2-resident)
#define PIX  32          // pixels per scatter block
#define EPSV 1e-05f
#define TSTRIDE 1064     // words per transpose tile (32*33 + 8 pad)

// Transposed accumulator scratch [CHUNK][HW][C] (32 MB, L2-resident; same
// addresses reused every chunk). g_att full size [Bs][HW]: each k_div block
// uniquely owns 32 entries. Zero-initialized at load; k_div restores zeros
// after consumption (separate pass AFTER reads complete — R3 lesson: never
// store to a line with a pending same-thread load miss), so graph replays are
// deterministic.
__device__ float g_feat[(size_t)CHUNK * HW * Cc];
__device__ float g_att[(size_t)Bs * HW];

// Tiny prefetch kernel: warms cw/cb in L2 and keeps the ncu -s window on
// k_scatter (diagnostics; negligible cost).
__global__ void k_pref(const float* __restrict__ cw, const float* __restrict__ cb) {
    float v = cw[threadIdx.x] + ((threadIdx.x < 3) ? cb[threadIdx.x] : 0.f);
    asm volatile("" :: "f"(v));
}

// -------------------------------------------- fused conv + scatter
// Register-resident x tile: thread (warp w, lane l) owns pixel hw0+l,
// channels 32w..32w+31 as 8 float4s (coalesced LDG, 128B/warp per channel).
// PRECISION (R8 lesson): the conv dot feeds round(dest) — boundary pixels
// flip on ~1e-7 changes in the sum. Per-4-channel products stay fp32, but
// group partials accumulate in fp64 (error ~2e-9, below the reference's own
// fp32 error), and the last-mile ops replicate the reference bit-for-bit in
// fp32: oa=(float)sum+cb; off=oa*128f; dest=(float)coord+off; rintf; clip.
// Scatter: 8x red.global.add.v4.f32 straight from registers.
__global__ __launch_bounds__(256) void k_scatter(
    const float* __restrict__ x, const float* __restrict__ cw,
    const float* __restrict__ cb, float* __restrict__ offo, int b0) {
    __shared__ float  s_w[3 * Cc];
    __shared__ double s_red[3 * 8 * 32];   // 6 KB, fp64 partials
    __shared__ float  s_att[PIX];
    __shared__ int    s_idx[PIX];

    const int tid  = threadIdx.x;
    const int lane = tid & 31;
    const int warp = tid >> 5;
    const int bl   = blockIdx.y;        // local batch (scratch index)
    const int b    = b0 + bl;           // global batch
    const int hw0  = blockIdx.x * PIX;

    for (int i = tid; i < 3 * Cc; i += 256) s_w[i] = cw[i];
    __syncthreads();

    const float* xb = x + (size_t)b * Cc * HW + hw0 + lane;
    float4 v[8];
    double a0 = 0.0, a1 = 0.0, a2 = 0.0;
#pragma unroll
    for (int r = 0; r < 8; r++) {
        const int c0 = warp * 32 + r * 4;
        float p0 = __ldg(xb + (size_t)(c0 + 0) * HW);
        float p1 = __ldg(xb + (size_t)(c0 + 1) * HW);
        float p2 = __ldg(xb + (size_t)(c0 + 2) * HW);
        float p3 = __ldg(xb + (size_t)(c0 + 3) * HW);
        v[r] = make_float4(p0, p1, p2, p3);
        // fp32 4-term group dots (cheap), accumulated exactly-ish in fp64
        float g0 = fmaf(p0, s_w[c0], fmaf(p1, s_w[c0 + 1],
                   fmaf(p2, s_w[c0 + 2], p3 * s_w[c0 + 3])));
        float g1 = fmaf(p0, s_w[Cc + c0], fmaf(p1, s_w[Cc + c0 + 1],
                   fmaf(p2, s_w[Cc + c0 + 2], p3 * s_w[Cc + c0 + 3])));
        float g2 = fmaf(p0, s_w[2 * Cc + c0], fmaf(p1, s_w[2 * Cc + c0 + 1],
                   fmaf(p2, s_w[2 * Cc + c0 + 2], p3 * s_w[2 * Cc + c0 + 3])));
        a0 += (double)g0;
        a1 += (double)g1;
        a2 += (double)g2;
    }
    s_red[(0 * 8 + warp) * 32 + lane] = a0;
    s_red[(1 * 8 + warp) * 32 + lane] = a1;
    s_red[(2 * 8 + warp) * 32 + lane] = a2;
    __syncthreads();

    if (warp == 0) {                    // lane == pixel within tile
        double r0 = 0.0, r1 = 0.0, r2 = 0.0;
#pragma unroll
        for (int w = 0; w < 8; w++) {
            r0 += s_red[w * 32 + lane];
            r1 += s_red[(8 + w) * 32 + lane];
            r2 += s_red[(16 + w) * 32 + lane];
        }
        // reference-matching fp32 last mile
        float oa0 = (float)r0 + cb[0];
        float oa1 = (float)r1 + cb[1];
        float oa2 = (float)r2 + cb[2];
        float offy = oa0 * (float)Hh;
        float offx = oa1 * (float)Ww;
        float att  = expf(oa2);
        int hw = hw0 + lane;
        int hh = hw >> 7, wc = hw & 127;
        int iy = (int)fminf(fmaxf(rintf((float)hh + offy), 0.f), 127.f);
        int ix = (int)fminf(fmaxf(rintf((float)wc + offx), 0.f), 127.f);
        int idx = (iy << 7) + ix;
        s_att[lane] = att;
        s_idx[lane] = idx;
        size_t ob = (size_t)b * 2 * HW + hw;       // offset: [B][2][H][W]
        offo[ob]      = offy;
        offo[ob + HW] = offx;
        atomicAdd(&g_att[(size_t)b * HW + idx], att);
    }
    __syncthreads();

    // Scatter straight from registers: this thread's pixel row, channel
    // segment 32*warp..32*warp+31, as 8 x red.global.add.v4.f32.
    const float att = s_att[lane];
    float* dst = g_feat + ((size_t)bl * HW + s_idx[lane]) * Cc + warp * 32;
#pragma unroll
    for (int r = 0; r < 8; r++) {
        asm volatile(
            "red.global.add.v4.f32 [%0], {%1, %2, %3, %4};" ::
            "l"(dst + r * 4),
            "f"(v[r].x * att), "f"(v[r].y * att),
            "f"(v[r].z * att), "f"(v[r].w * att)
            : "memory");
    }
}

// ----------------- normalize + transpose to [B][C][HW] + re-zero scratch
// Load phase: 8 independent coalesced LDG.128 per thread (MLP=8) into 8
// padded 32x33 smem tiles; ONE barrier. Store phase: warp g owns channel
// group g; lane (q=l>>2, jl=l&3) gathers 4 hw values per channel
// (conflict-free) and writes STG.128. inv applied per hw component.
__global__ __launch_bounds__(256) void k_div(float* __restrict__ out, int b0) {
    __shared__ float t[8 * TSTRIDE];    // ~34 KB
    __shared__ float inv[32];
    const int tid = threadIdx.x;
    const int bl  = blockIdx.y;
    const int b   = b0 + bl;
    const int hw0 = blockIdx.x * 32;

    if (tid < 32)
        inv[tid] = 1.0f / (g_att[(size_t)b * HW + hw0 + tid] + EPSV);

    const float4* src = reinterpret_cast<const float4*>(
        g_feat + ((size_t)bl * HW + hw0) * Cc);
#pragma unroll
    for (int k = 0; k < 8; k++) {
        int i  = tid + k * 256;         // [0, 2048)
        int hw = i >> 6;                // 0..31 (pixel)
        int cq = i & 63;                // float4 index within 256 channels
        float4 v = src[i];
        int g  = cq >> 3;               // channel group (tile)
        int cc = (cq & 7) * 4;          // channel within tile
        float* d = &t[g * TSTRIDE + hw * 33 + cc];
        d[0] = v.x; d[1] = v.y; d[2] = v.z; d[3] = v.w;
    }
    __syncthreads();

    const int lane = tid & 31;
    const int g    = tid >> 5;          // warp -> channel group
    const int q    = lane >> 2;         // hw quad (4q..4q+3)
    const int jl   = lane & 3;          // channel sub-lane
    const float4 iv = *reinterpret_cast<const float4*>(&inv[4 * q]);
    const float* tg = &t[g * TSTRIDE];
#pragma unroll
    for (int it = 0; it < 8; it++) {
        const int cc = it * 4 + jl;     // channel within group
        float4 o;
        o.x = tg[(4 * q + 0) * 33 + cc] * iv.x;
        o.y = tg[(4 * q + 1) * 33 + cc] * iv.y;
        o.z = tg[(4 * q + 2) * 33 + cc] * iv.z;
        o.w = tg[(4 * q + 3) * 33 + cc] * iv.w;
        *reinterpret_cast<float4*>(
            out + ((size_t)b * Cc + g * 32 + cc) * HW + hw0 + 4 * q) = o;
    }

    // Re-zero this block's scratch region (all loads above completed).
    float4* fz = reinterpret_cast<float4*>(g_feat + ((size_t)bl * HW + hw0) * Cc);
    float4 z = make_float4(0.f, 0.f, 0.f, 0.f);
#pragma unroll
    for (int k = 0; k < 8; k++)
        fz[tid + k * 256] = z;
    if (tid < 32)
        g_att[(size_t)b * HW + hw0 + tid] = 0.f;
}

// ---------------------------------------------------------------- launch
extern "C" void kernel_launch(void* const* d_in, const int* in_sizes, int n_in,
                              void* d_out, int out_size) {
    const float* x  = (const float*)d_in[0];   // [16,256,128,128]
    const float* cw = (const float*)d_in[1];   // [3,256]
    const float* cb = (const float*)d_in[2];   // [3]
    float* out  = (float*)d_out;                        // [B,C,HW]
    float* offo = out + (size_t)Bs * Cc * HW;           // [B,2,H,W]

    k_pref<<<1, 256>>>(cw, cb);
    for (int b0 = 0; b0 < Bs; b0 += CHUNK) {
        k_scatter<<<dim3(HW / PIX, CHUNK), 256>>>(x, cw, cb, offo, b0);
        k_div<<<dim3(HW / 32, CHUNK), 256>>>(out, b0);
    }
}

// round 10
// speedup vs baseline: 1.7689x; 1.7689x over previous
#include <cuda_runtime.h>
#include <math.h>

#define Bs   16
#define Cc   256
#define Hh   128
#define Ww   128
#define HW   16384
#define CHUNK 2          // batches per L2-blocked chunk (32MB scratch -> L2-resident)
#define PIX  32          // pixels per scatter block
#define SS   258         // smem row stride (words): even -> 8B-aligned LDS.64
#define EPSV 1e-05f
#define TSTRIDE 1064     // words per transpose tile (32*33 + 8 pad)

// Transposed accumulator scratch [CHUNK][HW][C] (32 MB, L2-resident; same
// addresses reused every chunk). g_att full size [Bs][HW]: each k_div block
// uniquely owns 32 entries. Zero-initialized at load; k_div restores zeros
// after consumption (separate pass AFTER reads complete — R3 lesson: never
// store to a line with a pending same-thread load miss), so graph replays are
// deterministic. Streaming data (x, out, offo) uses evict-first hints
// (__ldcs/__stcs) so it cannot evict the scratch from L2.
__device__ float g_feat[(size_t)CHUNK * HW * Cc];
__device__ float g_att[(size_t)Bs * HW];

// Tiny prefetch kernel: warms cw/cb in L2 and keeps the ncu -s window on
// k_scatter (diagnostics; negligible cost).
__global__ void k_pref(const float* __restrict__ cw, const float* __restrict__ cb) {
    float v = cw[threadIdx.x] + ((threadIdx.x < 3) ? cb[threadIdx.x] : 0.f);
    asm volatile("" :: "f"(v));
}

// -------------------------------------------- fused conv + scatter
// NUMERICS FROZEN (R8/R9 lesson): the strided-by-8 fp32 summation order
// (warp w owns channels {8k+w}, serial fmaf over k; cross-warp reduce in
// w-order seeded with cb) correlates with the reference's own fp32 rounding
// at the round(dest) boundaries -> rel_err 8.8778e-4 stable. Do not reorder.
__global__ __launch_bounds__(256) void k_scatter(
    const float* __restrict__ x, const float* __restrict__ cw,
    const float* __restrict__ cb, float* __restrict__ offo, int b0) {
    __shared__ float s_x[PIX * SS];     // 33 KB tile, [pixel][channel]
    __shared__ float s_w[3 * Cc];
    __shared__ float s_red[3 * 8 * 32];
    __shared__ float s_att[PIX];
    __shared__ int   s_idx[PIX];

    const int tid  = threadIdx.x;
    const int lane = tid & 31;
    const int warp = tid >> 5;
    const int bl   = blockIdx.y;        // local batch (scratch index)
    const int b    = b0 + bl;           // global batch
    const int hw0  = blockIdx.x * PIX;

    for (int i = tid; i < 3 * Cc; i += 256) s_w[i] = cw[i];
    __syncthreads();

    const float* xb = x + (size_t)b * Cc * HW + hw0;
    float a0 = 0.f, a1 = 0.f, a2 = 0.f;
#pragma unroll
    for (int k = 0; k < Cc / 8; k++) {
        int c = k * 8 + warp;                        // warp owns channel slice
        float v = __ldcs(xb + (size_t)c * HW + lane); // streaming: read-once x
        s_x[lane * SS + c] = v;
        a0 = fmaf(v, s_w[c],          a0);
        a1 = fmaf(v, s_w[Cc + c],     a1);
        a2 = fmaf(v, s_w[2 * Cc + c], a2);
    }
    s_red[(0 * 8 + warp) * 32 + lane] = a0;
    s_red[(1 * 8 + warp) * 32 + lane] = a1;
    s_red[(2 * 8 + warp) * 32 + lane] = a2;
    __syncthreads();

    if (warp == 0) {                    // lane == pixel within tile
        float r0 = cb[0], r1 = cb[1], r2 = cb[2];
#pragma unroll
        for (int w = 0; w < 8; w++) {
            r0 += s_red[w * 32 + lane];
            r1 += s_red[(8 + w) * 32 + lane];
            r2 += s_red[(16 + w) * 32 + lane];
        }
        float offy = r0 * (float)Hh;
        float offx = r1 * (float)Ww;
        float att  = expf(r2);
        int hw = hw0 + lane;
        int hh = hw >> 7, wc = hw & 127;
        // round-half-even (rintf) then clip, matching jnp.round + clip
        int iy = (int)fminf(fmaxf(rintf((float)hh + offy), 0.f), 127.f);
        int ix = (int)fminf(fmaxf(rintf((float)wc + offx), 0.f), 127.f);
        int idx = (iy << 7) + ix;
        s_att[lane] = att;
        s_idx[lane] = idx;
        size_t ob = (size_t)b * 2 * HW + hw;       // offset: [B][2][H][W]
        __stcs(offo + ob,      offy);              // streaming: write-once
        __stcs(offo + ob + HW, offx);
        atomicAdd(&g_att[(size_t)b * HW + idx], att);
    }
    __syncthreads();

    // Scatter: each warp handles 4 pixels; per pixel, 2 x red.v4 per lane
    // covering a contiguous 1KB destination row g_feat[bl][idx][:].
#pragma unroll
    for (int p = warp; p < PIX; p += 8) {
        float att = s_att[p];
        float* dst = g_feat + ((size_t)bl * HW + s_idx[p]) * Cc;
        const float* src = s_x + p * SS;
#pragma unroll
        for (int r = 0; r < 2; r++) {
            int c0 = r * 128 + 4 * lane;
            float2 u = *reinterpret_cast<const float2*>(src + c0);
            float2 v = *reinterpret_cast<const float2*>(src + c0 + 2);
            asm volatile(
                "red.global.add.v4.f32 [%0], {%1, %2, %3, %4};" ::
                "l"(dst + c0),
                "f"(u.x * att), "f"(u.y * att), "f"(v.x * att), "f"(v.y * att)
                : "memory");
        }
    }
}

// ----------------- normalize + transpose to [B][C][HW] + re-zero scratch
// Load phase: 8 independent coalesced LDG.128 per thread (MLP=8) into 8
// padded 32x33 smem tiles; ONE barrier. Store phase: warp g owns channel
// group g; lane (q=l>>2, jl=l&3) gathers 4 hw values per channel
// (conflict-free) and writes streaming STG.128. inv applied per hw component.
__global__ __launch_bounds__(256) void k_div(float* __restrict__ out, int b0) {
    __shared__ float t[8 * TSTRIDE];    // ~34 KB
    __shared__ float inv[32];
    const int tid = threadIdx.x;
    const int bl  = blockIdx.y;
    const int b   = b0 + bl;
    const int hw0 = blockIdx.x * 32;

    if (tid < 32)
        inv[tid] = 1.0f / (g_att[(size_t)b * HW + hw0 + tid] + EPSV);

    const float4* src = reinterpret_cast<const float4*>(
        g_feat + ((size_t)bl * HW + hw0) * Cc);
#pragma unroll
    for (int k = 0; k < 8; k++) {
        int i  = tid + k * 256;         // [0, 2048)
        int hw = i >> 6;                // 0..31 (pixel)
        int cq = i & 63;                // float4 index within 256 channels
        float4 v = src[i];
        int g  = cq >> 3;               // channel group (tile)
        int cc = (cq & 7) * 4;          // channel within tile
        float* d = &t[g * TSTRIDE + hw * 33 + cc];
        d[0] = v.x; d[1] = v.y; d[2] = v.z; d[3] = v.w;
    }
    __syncthreads();

    const int lane = tid & 31;
    const int g    = tid >> 5;          // warp -> channel group
    const int q    = lane >> 2;         // hw quad (4q..4q+3)
    const int jl   = lane & 3;          // channel sub-lane
    const float4 iv = *reinterpret_cast<const float4*>(&inv[4 * q]);
    const float* tg = &t[g * TSTRIDE];
#pragma unroll
    for (int it = 0; it < 8; it++) {
        const int cc = it * 4 + jl;     // channel within group
        float4 o;
        o.x = tg[(4 * q + 0) * 33 + cc] * iv.x;
        o.y = tg[(4 * q + 1) * 33 + cc] * iv.y;
        o.z = tg[(4 * q + 2) * 33 + cc] * iv.z;
        o.w = tg[(4 * q + 3) * 33 + cc] * iv.w;
        __stcs(reinterpret_cast<float4*>(
            out + ((size_t)b * Cc + g * 32 + cc) * HW + hw0 + 4 * q), o);
    }

    // Re-zero this block's scratch region (all loads above completed).
    float4* fz = reinterpret_cast<float4*>(g_feat + ((size_t)bl * HW + hw0) * Cc);
    float4 z = make_float4(0.f, 0.f, 0.f, 0.f);
#pragma unroll
    for (int k = 0; k < 8; k++)
        fz[tid + k * 256] = z;
    if (tid < 32)
        g_att[(size_t)b * HW + hw0 + tid] = 0.f;
}

// ---------------------------------------------------------------- launch
extern "C" void kernel_launch(void* const* d_in, const int* in_sizes, int n_in,
                              void* d_out, int out_size) {
    const float* x  = (const float*)d_in[0];   // [16,256,128,128]
    const float* cw = (const float*)d_in[1];   // [3,256]
    const float* cb = (const float*)d_in[2];   // [3]
    float* out  = (float*)d_out;                        // [B,C,HW]
    float* offo = out + (size_t)Bs * Cc * HW;           // [B,2,H,W]

    k_pref<<<1, 256>>>(cw, cb);
    for (int b0 = 0; b0 < Bs; b0 += CHUNK) {
        k_scatter<<<dim3(HW / PIX, CHUNK), 256>>>(x, cw, cb, offo, b0);
        k_div<<<dim3(HW / 32, CHUNK), 256>>>(out, b0);
    }
}

// round 11
// speedup vs baseline: 2.0901x; 1.1816x over previous
#include <cuda_runtime.h>
#include <math.h>

#define Bs   16
#define Cc   256
#define Hh   128
#define Ww   128
#define HW   16384
#define CHUNK 2          // batches per chunk (32MB scratch half -> L2-resident)
#define PIX  32          // pixels per scatter block
#define SS   258         // smem row stride (words): even -> 8B-aligned LDS.64
#define EPSV 1e-05f
#define TSTRIDE 1064     // words per transpose tile (32*33 + 8 pad)

// TWO ping-pong scratch halves [2][CHUNK][HW][C] (32 MB each): even chunks use
// half 0 on the origin stream, odd chunks use half 1 on a second stream, so
// div(chunk i) overlaps scatter(chunk i+1). g_att full size [Bs][HW] (batch-
// disjoint across chains). Zero-initialized at load; k_div restores zeros
// after consumption (separate pass AFTER reads complete — R3 lesson), so
// graph replays are deterministic. Streaming data (x, out, offo) uses
// evict-first hints (__ldcs/__stcs) so it cannot evict scratch from L2.
__device__ float g_feat[(size_t)2 * CHUNK * HW * Cc];
__device__ float g_att[(size_t)Bs * HW];

// -------------------------------------------- fused conv + scatter
// NUMERICS FROZEN (R8/R9 lesson): the strided-by-8 fp32 summation order
// (warp w owns channels {8k+w}, serial fmaf over k; cross-warp reduce in
// w-order seeded with cb) correlates with the reference's own fp32 rounding
// at the round(dest) boundaries -> rel_err 8.8778e-4 stable. Do not reorder.
__global__ __launch_bounds__(256) void k_scatter(
    const float* __restrict__ x, const float* __restrict__ cw,
    const float* __restrict__ cb, float* __restrict__ offo, int b0, int half) {
    __shared__ float s_x[PIX * SS];     // 33 KB tile, [pixel][channel]
    __shared__ float s_w[3 * Cc];
    __shared__ float s_red[3 * 8 * 32];
    __shared__ float s_att[PIX];
    __shared__ int   s_idx[PIX];

    const int tid  = threadIdx.x;
    const int lane = tid & 31;
    const int warp = tid >> 5;
    const int bl   = blockIdx.y;        // local batch within chunk
    const int b    = b0 + bl;           // global batch
    const int hw0  = blockIdx.x * PIX;
    float* feat = g_feat + (size_t)(half * CHUNK + bl) * HW * Cc;

    for (int i = tid; i < 3 * Cc; i += 256) s_w[i] = cw[i];
    __syncthreads();

    const float* xb = x + (size_t)b * Cc * HW + hw0;
    float a0 = 0.f, a1 = 0.f, a2 = 0.f;
#pragma unroll
    for (int k = 0; k < Cc / 8; k++) {
        int c = k * 8 + warp;                         // warp owns channel slice
        float v = __ldcs(xb + (size_t)c * HW + lane); // streaming: read-once x
        s_x[lane * SS + c] = v;
        a0 = fmaf(v, s_w[c],          a0);
        a1 = fmaf(v, s_w[Cc + c],     a1);
        a2 = fmaf(v, s_w[2 * Cc + c], a2);
    }
    s_red[(0 * 8 + warp) * 32 + lane] = a0;
    s_red[(1 * 8 + warp) * 32 + lane] = a1;
    s_red[(2 * 8 + warp) * 32 + lane] = a2;
    __syncthreads();

    if (warp == 0) {                    // lane == pixel within tile
        float r0 = cb[0], r1 = cb[1], r2 = cb[2];
#pragma unroll
        for (int w = 0; w < 8; w++) {
            r0 += s_red[w * 32 + lane];
            r1 += s_red[(8 + w) * 32 + lane];
            r2 += s_red[(16 + w) * 32 + lane];
        }
        float offy = r0 * (float)Hh;
        float offx = r1 * (float)Ww;
        float att  = expf(r2);
        int hw = hw0 + lane;
        int hh = hw >> 7, wc = hw & 127;
        // round-half-even (rintf) then clip, matching jnp.round + clip
        int iy = (int)fminf(fmaxf(rintf((float)hh + offy), 0.f), 127.f);
        int ix = (int)fminf(fmaxf(rintf((float)wc + offx), 0.f), 127.f);
        int idx = (iy << 7) + ix;
        s_att[lane] = att;
        s_idx[lane] = idx;
        size_t ob = (size_t)b * 2 * HW + hw;       // offset: [B][2][H][W]
        __stcs(offo + ob,      offy);              // streaming: write-once
        __stcs(offo + ob + HW, offx);
        atomicAdd(&g_att[(size_t)b * HW + idx], att);
    }
    __syncthreads();

    // Scatter: each warp handles 4 pixels; per pixel, 2 x red.v4 per lane
    // covering a contiguous 1KB destination row feat[idx][:].
#pragma unroll
    for (int p = warp; p < PIX; p += 8) {
        float att = s_att[p];
        float* dst = feat + (size_t)s_idx[p] * Cc;
        const float* src = s_x + p * SS;
#pragma unroll
        for (int r = 0; r < 2; r++) {
            int c0 = r * 128 + 4 * lane;
            float2 u = *reinterpret_cast<const float2*>(src + c0);
            float2 v = *reinterpret_cast<const float2*>(src + c0 + 2);
            asm volatile(
                "red.global.add.v4.f32 [%0], {%1, %2, %3, %4};" ::
                "l"(dst + c0),
                "f"(u.x * att), "f"(u.y * att), "f"(v.x * att), "f"(v.y * att)
                : "memory");
        }
    }
}

// ----------------- normalize + transpose to [B][C][HW] + re-zero scratch
// Load phase: 8 independent coalesced LDG.128 per thread (MLP=8) into 8
// padded 32x33 smem tiles; ONE barrier. Store phase: warp g owns channel
// group g; lane (q=l>>2, jl=l&3) gathers 4 hw values per channel
// (conflict-free) and writes streaming STG.128. inv applied per hw component.
__global__ __launch_bounds__(256) void k_div(float* __restrict__ out, int b0,
                                             int half) {
    __shared__ float t[8 * TSTRIDE];    // ~34 KB
    __shared__ float inv[32];
    const int tid = threadIdx.x;
    const int bl  = blockIdx.y;
    const int b   = b0 + bl;
    const int hw0 = blockIdx.x * 32;
    float* feat = g_feat + (size_t)(half * CHUNK + bl) * HW * Cc;

    if (tid < 32)
        inv[tid] = 1.0f / (g_att[(size_t)b * HW + hw0 + tid] + EPSV);

    const float4* src = reinterpret_cast<const float4*>(feat + (size_t)hw0 * Cc);
#pragma unroll
    for (int k = 0; k < 8; k++) {
        int i  = tid + k * 256;         // [0, 2048)
        int hw = i >> 6;                // 0..31 (pixel)
        int cq = i & 63;                // float4 index within 256 channels
        float4 v = src[i];
        int g  = cq >> 3;               // channel group (tile)
        int cc = (cq & 7) * 4;          // channel within tile
        float* d = &t[g * TSTRIDE + hw * 33 + cc];
        d[0] = v.x; d[1] = v.y; d[2] = v.z; d[3] = v.w;
    }
    __syncthreads();

    const int lane = tid & 31;
    const int g    = tid >> 5;          // warp -> channel group
    const int q    = lane >> 2;         // hw quad (4q..4q+3)
    const int jl   = lane & 3;          // channel sub-lane
    const float4 iv = *reinterpret_cast<const float4*>(&inv[4 * q]);
    const float* tg = &t[g * TSTRIDE];
#pragma unroll
    for (int it = 0; it < 8; it++) {
        const int cc = it * 4 + jl;     // channel within group
        float4 o;
        o.x = tg[(4 * q + 0) * 33 + cc] * iv.x;
        o.y = tg[(4 * q + 1) * 33 + cc] * iv.y;
        o.z = tg[(4 * q + 2) * 33 + cc] * iv.z;
        o.w = tg[(4 * q + 3) * 33 + cc] * iv.w;
        __stcs(reinterpret_cast<float4*>(
            out + ((size_t)b * Cc + g * 32 + cc) * HW + hw0 + 4 * q), o);
    }

    // Re-zero this block's scratch region (all loads above completed).
    float4* fz = reinterpret_cast<float4*>(feat + (size_t)hw0 * Cc);
    float4 z = make_float4(0.f, 0.f, 0.f, 0.f);
#pragma unroll
    for (int k = 0; k < 8; k++)
        fz[tid + k * 256] = z;
    if (tid < 32)
        g_att[(size_t)b * HW + hw0 + tid] = 0.f;
}

// ---------------------------------------------------------------- launch
// Two independent chains: even chunks (scratch half 0) stay on the origin
// stream; odd chunks (half 1) run on a second stream via the standard
// capture-safe event fork/join. No cross-chain data dependency (distinct
// batches, distinct scratch halves), so div(i) overlaps scatter(i+1).
extern "C" void kernel_launch(void* const* d_in, const int* in_sizes, int n_in,
                              void* d_out, int out_size) {
    const float* x  = (const float*)d_in[0];   // [16,256,128,128]
    const float* cw = (const float*)d_in[1];   // [3,256]
    const float* cb = (const float*)d_in[2];   // [3]
    float* out  = (float*)d_out;                        // [B,C,HW]
    float* offo = out + (size_t)Bs * Cc * HW;           // [B,2,H,W]

    static cudaStream_t s2 = nullptr;
    static cudaEvent_t  efork = nullptr, ejoin = nullptr;
    if (s2 == nullptr) {               // host-side resource init only; the GPU
        cudaStreamCreateWithFlags(&s2, cudaStreamNonBlocking);  // work issued
        cudaEventCreateWithFlags(&efork, cudaEventDisableTiming); // per call is
        cudaEventCreateWithFlags(&ejoin, cudaEventDisableTiming); // identical
    }

    cudaEventRecord(efork, 0);
    cudaStreamWaitEvent(s2, efork, 0);

    for (int c = 0; c < Bs / CHUNK; c++) {
        const int half = c & 1;
        const int b0   = c * CHUNK;
        cudaStream_t st = half ? s2 : (cudaStream_t)0;
        k_scatter<<<dim3(HW / PIX, CHUNK), 256, 0, st>>>(x, cw, cb, offo, b0, half);
        k_div<<<dim3(HW / 32, CHUNK), 256, 0, st>>>(out, b0, half);
    }

    cudaEventRecord(ejoin, s2);
    cudaStreamWaitEvent((cudaStream_t)0, ejoin, 0);
}

// round 12
// speedup vs baseline: 2.0917x; 1.0008x over previous
#include <cuda_runtime.h>
#include <math.h>

#define Bs   16
#define Cc   256
#define Hh   128
#define Ww   128
#define HW   16384
#define NSLC 4           // ping-pong scratch slices / streams
#define PIX  32          // pixels per scatter block
#define SS   258         // smem row stride (words): even -> 8B-aligned LDS.64
#define EPSV 1e-05f
#define TSTRIDE 1064     // words per transpose tile (32*33 + 8 pad)

// FOUR ping-pong scratch slices [NSLC][HW][C] (16 MB each, 64 MB total,
// L2-resident): batch c uses slice c%4 on stream c%4, so up to 4 independent
// (scatter,div) pairs co-run. g_att full size [Bs][HW] (batch-disjoint).
// Zero-initialized at load; k_div restores zeros after consumption (separate
// pass AFTER reads complete — R3 lesson: never store to a line with a pending
// same-thread load miss), so graph replays are deterministic. Streaming data
// (x, out, offo) uses evict-first hints (__ldcs/__stcs) so it cannot evict
// scratch from L2.
__device__ float g_feat[(size_t)NSLC * HW * Cc];
__device__ float g_att[(size_t)Bs * HW];

// -------------------------------------------- fused conv + scatter
// NUMERICS FROZEN (R8/R9 lesson): the strided-by-8 fp32 summation order
// (warp w owns channels {8k+w}, serial fmaf over k; cross-warp reduce in
// w-order seeded with cb) correlates with the reference's own fp32 rounding
// at the round(dest) boundaries -> rel_err 8.8778e-4 stable. Do not reorder.
__global__ __launch_bounds__(256) void k_scatter(
    const float* __restrict__ x, const float* __restrict__ cw,
    const float* __restrict__ cb, float* __restrict__ offo, int b, int slc) {
    __shared__ float s_x[PIX * SS];     // 33 KB tile, [pixel][channel]
    __shared__ float s_w[3 * Cc];
    __shared__ float s_red[3 * 8 * 32];
    __shared__ float s_att[PIX];
    __shared__ int   s_idx[PIX];

    const int tid  = threadIdx.x;
    const int lane = tid & 31;
    const int warp = tid >> 5;
    const int hw0  = blockIdx.x * PIX;
    float* feat = g_feat + (size_t)slc * HW * Cc;

    for (int i = tid; i < 3 * Cc; i += 256) s_w[i] = cw[i];
    __syncthreads();

    const float* xb = x + (size_t)b * Cc * HW + hw0;
    float a0 = 0.f, a1 = 0.f, a2 = 0.f;
#pragma unroll
    for (int k = 0; k < Cc / 8; k++) {
        int c = k * 8 + warp;                         // warp owns channel slice
        float v = __ldcs(xb + (size_t)c * HW + lane); // streaming: read-once x
        s_x[lane * SS + c] = v;
        a0 = fmaf(v, s_w[c],          a0);
        a1 = fmaf(v, s_w[Cc + c],     a1);
        a2 = fmaf(v, s_w[2 * Cc + c], a2);
    }
    s_red[(0 * 8 + warp) * 32 + lane] = a0;
    s_red[(1 * 8 + warp) * 32 + lane] = a1;
    s_red[(2 * 8 + warp) * 32 + lane] = a2;
    __syncthreads();

    if (warp == 0) {                    // lane == pixel within tile
        float r0 = cb[0], r1 = cb[1], r2 = cb[2];
#pragma unroll
        for (int w = 0; w < 8; w++) {
            r0 += s_red[w * 32 + lane];
            r1 += s_red[(8 + w) * 32 + lane];
            r2 += s_red[(16 + w) * 32 + lane];
        }
        float offy = r0 * (float)Hh;
        float offx = r1 * (float)Ww;
        float att  = expf(r2);
        int hw = hw0 + lane;
        int hh = hw >> 7, wc = hw & 127;
        // round-half-even (rintf) then clip, matching jnp.round + clip
        int iy = (int)fminf(fmaxf(rintf((float)hh + offy), 0.f), 127.f);
        int ix = (int)fminf(fmaxf(rintf((float)wc + offx), 0.f), 127.f);
        int idx = (iy << 7) + ix;
        s_att[lane] = att;
        s_idx[lane] = idx;
        size_t ob = (size_t)b * 2 * HW + hw;       // offset: [B][2][H][W]
        __stcs(offo + ob,      offy);              // streaming: write-once
        __stcs(offo + ob + HW, offx);
        atomicAdd(&g_att[(size_t)b * HW + idx], att);
    }
    __syncthreads();

    // Scatter: each warp handles 4 pixels; per pixel, 2 x red.v4 per lane
    // covering a contiguous 1KB destination row feat[idx][:].
#pragma unroll
    for (int p = warp; p < PIX; p += 8) {
        float att = s_att[p];
        float* dst = feat + (size_t)s_idx[p] * Cc;
        const float* src = s_x + p * SS;
#pragma unroll
        for (int r = 0; r < 2; r++) {
            int c0 = r * 128 + 4 * lane;
            float2 u = *reinterpret_cast<const float2*>(src + c0);
            float2 v = *reinterpret_cast<const float2*>(src + c0 + 2);
            asm volatile(
                "red.global.add.v4.f32 [%0], {%1, %2, %3, %4};" ::
                "l"(dst + c0),
                "f"(u.x * att), "f"(u.y * att), "f"(v.x * att), "f"(v.y * att)
                : "memory");
        }
    }
}

// ----------------- normalize + transpose to [B][C][HW] + re-zero scratch
// Load phase: 8 independent coalesced LDG.128 per thread (MLP=8) into 8
// padded 32x33 smem tiles; ONE barrier. Store phase: warp g owns channel
// group g; lane (q=l>>2, jl=l&3) gathers 4 hw values per channel
// (conflict-free) and writes streaming STG.128. inv applied per hw component.
__global__ __launch_bounds__(256) void k_div(float* __restrict__ out, int b,
                                             int slc) {
    __shared__ float t[8 * TSTRIDE];    // ~34 KB
    __shared__ float inv[32];
    const int tid = threadIdx.x;
    const int hw0 = blockIdx.x * 32;
    float* feat = g_feat + (size_t)slc * HW * Cc;

    if (tid < 32)
        inv[tid] = 1.0f / (g_att[(size_t)b * HW + hw0 + tid] + EPSV);

    const float4* src = reinterpret_cast<const float4*>(feat + (size_t)hw0 * Cc);
#pragma unroll
    for (int k = 0; k < 8; k++) {
        int i  = tid + k * 256;         // [0, 2048)
        int hw = i >> 6;                // 0..31 (pixel)
        int cq = i & 63;                // float4 index within 256 channels
        float4 v = src[i];
        int g  = cq >> 3;               // channel group (tile)
        int cc = (cq & 7) * 4;          // channel within tile
        float* d = &t[g * TSTRIDE + hw * 33 + cc];
        d[0] = v.x; d[1] = v.y; d[2] = v.z; d[3] = v.w;
    }
    __syncthreads();

    const int lane = tid & 31;
    const int g    = tid >> 5;          // warp -> channel group
    const int q    = lane >> 2;         // hw quad (4q..4q+3)
    const int jl   = lane & 3;          // channel sub-lane
    const float4 iv = *reinterpret_cast<const float4*>(&inv[4 * q]);
    const float* tg = &t[g * TSTRIDE];
#pragma unroll
    for (int it = 0; it < 8; it++) {
        const int cc = it * 4 + jl;     // channel within group
        float4 o;
        o.x = tg[(4 * q + 0) * 33 + cc] * iv.x;
        o.y = tg[(4 * q + 1) * 33 + cc] * iv.y;
        o.z = tg[(4 * q + 2) * 33 + cc] * iv.z;
        o.w = tg[(4 * q + 3) * 33 + cc] * iv.w;
        __stcs(reinterpret_cast<float4*>(
            out + ((size_t)b * Cc + g * 32 + cc) * HW + hw0 + 4 * q), o);
    }

    // Re-zero this block's scratch region (all loads above completed).
    float4* fz = reinterpret_cast<float4*>(feat + (size_t)hw0 * Cc);
    float4 z = make_float4(0.f, 0.f, 0.f, 0.f);
#pragma unroll
    for (int k = 0; k < 8; k++)
        fz[tid + k * 256] = z;
    if (tid < 32)
        g_att[(size_t)b * HW + hw0 + tid] = 0.f;
}

// ---------------------------------------------------------------- launch
// 16 independent (scatter,div) pairs, one batch each, round-robin over 4
// streams (origin + 3) with capture-safe event fork/join. Scratch slice
// reuse within a stream is ordered by stream order.
extern "C" void kernel_launch(void* const* d_in, const int* in_sizes, int n_in,
                              void* d_out, int out_size) {
    const float* x  = (const float*)d_in[0];   // [16,256,128,128]
    const float* cw = (const float*)d_in[1];   // [3,256]
    const float* cb = (const float*)d_in[2];   // [3]
    float* out  = (float*)d_out;                        // [B,C,HW]
    float* offo = out + (size_t)Bs * Cc * HW;           // [B,2,H,W]

    static cudaStream_t st[NSLC] = {nullptr, nullptr, nullptr, nullptr};
    static cudaEvent_t  efork = nullptr;
    static cudaEvent_t  ejoin[NSLC] = {nullptr, nullptr, nullptr, nullptr};
    if (efork == nullptr) {            // host-side resource init only
        st[0] = (cudaStream_t)0;       // capture-origin stream
        cudaEventCreateWithFlags(&efork, cudaEventDisableTiming);
        for (int i = 1; i < NSLC; i++) {
            cudaStreamCreateWithFlags(&st[i], cudaStreamNonBlocking);
            cudaEventCreateWithFlags(&ejoin[i], cudaEventDisableTiming);
        }
    }

    cudaEventRecord(efork, st[0]);
    for (int i = 1; i < NSLC; i++)
        cudaStreamWaitEvent(st[i], efork, 0);

    for (int b = 0; b < Bs; b++) {
        const int s = b & (NSLC - 1);
        k_scatter<<<HW / PIX, 256, 0, st[s]>>>(x, cw, cb, offo, b, s);
        k_div<<<HW / 32, 256, 0, st[s]>>>(out, b, s);
    }

    for (int i = 1; i < NSLC; i++) {
        cudaEventRecord(ejoin[i], st[i]);
        cudaStreamWaitEvent(st[0], ejoin[i], 0);
    }
}